// round 15
// baseline (speedup 1.0000x reference)
#include <cuda_runtime.h>
#include <stdint.h>
#include <math.h>

#define B_     32768
#define D_IN_  256
#define D_OUT_ 256
#define E_     8
#define H_     512
#define GH_    128
#define CAP_   32768

// ---------------- scratch (static __device__, no allocation) ----------------
__device__ int   g_counts[E_];
__device__ int   g_list[E_ * B_];
__device__ int   g_pos[B_ * 2];                     // token -> (e*CAP+row) x2
__device__ float g_wtk[B_ * 2];                     // token -> combine weights x2
__device__ float g_h1[(size_t)E_ * CAP_ * H_];      // layer-1 acts; reused as y3 [.][256]
__device__ float g_h2[(size_t)E_ * CAP_ * H_];      // layer-2 acts
__device__ float g_wT1[(size_t)E_ * H_ * D_IN_];    // We1^T tf32
__device__ float g_wT2[(size_t)E_ * H_ * H_];       // We2^T tf32
__device__ float g_wT3[(size_t)E_ * D_OUT_ * H_];   // We3^T tf32

// ---------------- helpers ----------------
__device__ __forceinline__ uint32_t smem_u32(const void* p) {
    uint32_t a;
    asm("{ .reg .u64 t; cvta.to.shared.u64 t, %1; cvt.u32.u64 %0, t; }" : "=r"(a) : "l"(p));
    return a;
}
__device__ __forceinline__ uint32_t f2tf(float x) {
    uint32_t u;
    asm("cvt.rna.tf32.f32 %0, %1;" : "=r"(u) : "f"(x));
    return u;
}
__device__ __forceinline__ void cp16(uint32_t dst, const float* src) {
    asm volatile("cp.async.cg.shared.global [%0], [%1], 16;"
                 :: "r"(dst), "l"(__cvta_generic_to_global(src)) : "memory");
}
#define CP_COMMIT() asm volatile("cp.async.commit_group;" ::: "memory")
#define CP_WAIT1()  asm volatile("cp.async.wait_group 1;" ::: "memory")

__device__ __forceinline__ void ldsm4(uint32_t* r, uint32_t a) {
    asm volatile("ldmatrix.sync.aligned.m8n8.x4.shared.b16 {%0,%1,%2,%3}, [%4];"
                 : "=r"(r[0]), "=r"(r[1]), "=r"(r[2]), "=r"(r[3]) : "r"(a));
}
__device__ __forceinline__ void mma8(float* d, const uint32_t* a, const uint32_t* b) {
    asm volatile(
        "mma.sync.aligned.m16n8k8.row.col.f32.tf32.tf32.f32 "
        "{%0,%1,%2,%3},{%4,%5,%6,%7},{%8,%9},{%0,%1,%2,%3};\n"
        : "+f"(d[0]), "+f"(d[1]), "+f"(d[2]), "+f"(d[3])
        : "r"(a[0]), "r"(a[1]), "r"(a[2]), "r"(a[3]), "r"(b[0]), "r"(b[1]));
}

#define AP 36

// ---------------- one-shot: all 3 weight transposes (tf32 round) + counter zero ----------------
__global__ void __launch_bounds__(256) transpose_all(
    const float* __restrict__ We1, const float* __restrict__ We2,
    const float* __restrict__ We3)
{
    __shared__ float t[32][33];
    const int sel = blockIdx.z >> 3, e = blockIdx.z & 7;
    const int K = (sel == 0) ? 256 : 512;
    const int N = (sel == 2) ? 256 : 512;
    if (blockIdx.x * 32 >= K || blockIdx.y * 32 >= N) return;
    if (blockIdx.x == 0 && blockIdx.y == 0 && blockIdx.z == 0 && threadIdx.x < E_)
        g_counts[threadIdx.x] = 0;
    const float* I = ((sel == 0) ? We1 : (sel == 1) ? We2 : We3) + (size_t)e * K * N;
    float* O = ((sel == 0) ? g_wT1 : (sel == 1) ? g_wT2 : g_wT3) + (size_t)e * K * N;
    const int k0 = blockIdx.x * 32, n0 = blockIdx.y * 32;
    const int tx = threadIdx.x & 31, ty = threadIdx.x >> 5;
    #pragma unroll
    for (int p = 0; p < 32; p += 8)
        t[ty + p][tx] = I[(size_t)(k0 + ty + p) * N + n0 + tx];
    __syncthreads();
    #pragma unroll
    for (int p = 0; p < 32; p += 8)
        O[(size_t)(n0 + ty + p) * K + k0 + tx] = __uint_as_float(f2tf(t[tx][ty + p]));
}

// ---------------- gating: register-tiled fp32 SGEMM (proven r11), routing bit-identical ----------------
#define GATE_DSMEM (128 * 132 * 4)
__global__ void __launch_bounds__(256, 2) gating_kernel(
    const float* __restrict__ x,  const float* __restrict__ gW1,
    const float* __restrict__ gb1, const float* __restrict__ gW2,
    const float* __restrict__ gb2)
{
    extern __shared__ float dsm[];            // staging As[8][132]+Bs[8][132]; later h[128][132]
    float* As = dsm;
    float* Bs = dsm + 8 * 132;
    __shared__ float b1s[GH_], w2s[GH_ * E_], b2s[E_], logt[128 * E_];

    const int tid = threadIdx.x;
    const int tok0 = blockIdx.x * 128;
    if (tid < GH_) b1s[tid] = gb1[tid];
    for (int i = tid; i < GH_ * E_; i += 256) w2s[i] = gW2[i];
    if (tid < E_) b2s[tid] = gb2[tid];

    const int m_ld = tid & 127, half = tid >> 7;
    const int kb_ld = tid >> 5, j_ld = (tid & 31) * 4;
    const int tx = tid & 15, ty = tid >> 4;
    const int ma = ty * 4, jb = tx * 4;

    float acc[8][8];
    #pragma unroll
    for (int i = 0; i < 8; ++i)
        #pragma unroll
        for (int j = 0; j < 8; ++j) acc[i][j] = 0.f;

    for (int kt = 0; kt < 32; ++kt) {
        const int k0 = kt * 8;
        float4 xa = *(const float4*)(x + (size_t)(tok0 + m_ld) * D_IN_ + k0 + half * 4);
        float4 wb = *(const float4*)(gW1 + (size_t)(k0 + kb_ld) * GH_ + j_ld);
        __syncthreads();
        As[(half * 4 + 0) * 132 + m_ld] = xa.x;
        As[(half * 4 + 1) * 132 + m_ld] = xa.y;
        As[(half * 4 + 2) * 132 + m_ld] = xa.z;
        As[(half * 4 + 3) * 132 + m_ld] = xa.w;
        *(float4*)(Bs + kb_ld * 132 + j_ld) = wb;
        __syncthreads();

        #pragma unroll
        for (int g = 0; g < 2; ++g) {
            #pragma unroll
            for (int kk = 3; kk >= 0; --kk) {
                const int k = g * 4 + kk;
                float4 a0 = *(const float4*)(As + k * 132 + ma);
                float4 a1 = *(const float4*)(As + k * 132 + 64 + ma);
                float4 b0 = *(const float4*)(Bs + k * 132 + jb);
                float4 b1 = *(const float4*)(Bs + k * 132 + 64 + jb);
                const float av[8] = {a0.x, a0.y, a0.z, a0.w, a1.x, a1.y, a1.z, a1.w};
                const float bv[8] = {b0.x, b0.y, b0.z, b0.w, b1.x, b1.y, b1.z, b1.w};
                #pragma unroll
                for (int i = 0; i < 8; ++i)
                    #pragma unroll
                    for (int j = 0; j < 8; ++j)
                        acc[i][j] = fmaf(av[i], bv[j], acc[i][j]);
            }
        }
    }
    __syncthreads();

    float* hsm = dsm;
    #pragma unroll
    for (int i = 0; i < 8; ++i) {
        const int m = ma + (i & 3) + (i >> 2) * 64;
        #pragma unroll
        for (int j = 0; j < 8; ++j) {
            const int jj = jb + (j & 3) + (j >> 2) * 64;
            hsm[m * 132 + jj] = fmaxf(acc[i][j] + b1s[jj], 0.f);
        }
    }
    __syncthreads();

    #pragma unroll
    for (int q = 0; q < 4; ++q) {
        const int pid = tid + q * 256;
        const int tok = pid >> 3, ee = pid & 7;
        float a = b2s[ee];
        const float* hrow = hsm + tok * 132;
        #pragma unroll 8
        for (int h = 0; h < 128; ++h) a = fmaf(hrow[h], w2s[h * 8 + ee], a);
        logt[tok * 8 + ee] = a;
    }
    __syncthreads();

    if (tid < 128) {
        float l[8];
        #pragma unroll
        for (int q = 0; q < 8; ++q) l[q] = logt[tid * 8 + q];
        int i1 = 0; float m1 = l[0];
        #pragma unroll
        for (int q = 1; q < 8; ++q) if (l[q] > m1) { m1 = l[q]; i1 = q; }
        int i2 = -1; float m2 = -1e30f;
        #pragma unroll
        for (int q = 0; q < 8; ++q) if (q != i1 && l[q] > m2) { m2 = l[q]; i2 = q; }
        const int t = tok0 + tid;
        const float ex  = expf(m2 - m1);
        const float den = 1.f + ex;
        int p1 = atomicAdd(&g_counts[i1], 1);
        g_list[i1 * B_ + p1] = t;
        int p2 = atomicAdd(&g_counts[i2], 1);
        g_list[i2 * B_ + p2] = t;
        g_pos[t * 2]     = i1 * CAP_ + p1;
        g_pos[t * 2 + 1] = i2 * CAP_ + p2;
        g_wtk[t * 2]     = 1.f / den;
        g_wtk[t * 2 + 1] = ex / den;
    }
}

// ---------------- tf32 mma.sync GEMM: block 128x256, 2x4 warps of 64x64, BK=32, 3 stages ----------------
#define A_STG_B     18432             // 128*36*4
#define STAGE_BYTES 55296             // A + B (256*36*4 = 36864)
#define GEMM_DSMEM  165888            // 3 stages

template<int K, int NTOT, int STAGE, bool RELU, bool TFROUND>
__global__ void __launch_bounds__(256) gemm_mma(const float* __restrict__ bias,
                                                const float* __restrict__ xsrc)
{
    const int e = blockIdx.z;
    const int cnt = g_counts[e];
    const int row0 = blockIdx.y * 128;     // y = row tile
    if (row0 >= cnt) return;
    const int n0 = blockIdx.x * 256;       // x = n tile

    extern __shared__ float dsm[];
    const uint32_t smBase = smem_u32(dsm);
    __shared__ int stok[128];

    const int tid = threadIdx.x;
    const int lid = tid & 31, wid = tid >> 5;
    const int g = lid >> 2, tg = lid & 3;
    const int wm = wid >> 2, wn = wid & 3;     // 2 x 4 warps of 64x64
    const int mb = wm * 64,  nb = wn * 64;

    const float* A  = (STAGE == 1) ? xsrc  : (STAGE == 2) ? g_h1 : g_h2;
    const float* Wt = (STAGE == 1) ? g_wT1 : (STAGE == 2) ? g_wT2 : g_wT3;
    float* Y = (STAGE == 1) ? g_h1 : (STAGE == 2) ? g_h2 : g_h1;   // stage3: y rows [.][256]
    const float* Ab = A + ((STAGE == 1) ? 0 : ((size_t)e * CAP_ + row0) * K);
    const float* Bb = Wt + ((size_t)e * NTOT + n0) * K;

    if (STAGE == 1) {   // index table: tile row -> token row of x
        if (tid < 128) {
            int r = row0 + tid;
            stok[tid] = (r < cnt) ? g_list[e * B_ + r] : 0;
        }
        __syncthreads();
    }

    const int lane_row = (lid & 7) + (((lid >> 3) & 1) << 3);
    const int lane_k   = (lid >> 4) * 4;
    uint32_t aAddr[4], bAddr[4];
    #pragma unroll
    for (int f = 0; f < 4; ++f)
        aAddr[f] = smBase + ((mb + f * 16 + lane_row) * AP + lane_k) * 4;
    {
        const int grp = lid >> 3;
        #pragma unroll
        for (int p = 0; p < 4; ++p) {
            const int n_loc = nb + (2 * p + (grp >> 1)) * 8 + (lid & 7);
            const int kcol  = (grp & 1) * 4;
            bAddr[p] = smBase + A_STG_B + (n_loc * AP + kcol) * 4;
        }
    }

    float acc[4][8][4];
    #pragma unroll
    for (int f = 0; f < 4; ++f)
        #pragma unroll
        for (int j = 0; j < 8; ++j)
            #pragma unroll
            for (int q = 0; q < 4; ++q) acc[f][j][q] = 0.f;

    // staging: A 1024 float4 (4/thread), B 2048 float4 (8/thread)
    auto stage_copy = [&](int buf, int kt) {
        const uint32_t sb = smBase + buf * STAGE_BYTES;
        const int k0 = kt * 32;
        #pragma unroll
        for (int q = 0; q < 4; ++q) {
            const int c = q * 256 + tid;
            const int r = c >> 3, gg = (c & 7) * 4;
            const float* srcA = (STAGE == 1)
                ? Ab + (size_t)stok[r] * K + k0 + gg
                : Ab + (size_t)r * K + k0 + gg;
            cp16(sb + (r * AP + gg) * 4, srcA);
        }
        #pragma unroll
        for (int q = 0; q < 8; ++q) {
            const int c = q * 256 + tid;
            const int r = c >> 3, gg = (c & 7) * 4;
            cp16(sb + A_STG_B + (r * AP + gg) * 4, Bb + (size_t)r * K + k0 + gg);
        }
    };

    constexpr int KT = K / 32;
    stage_copy(0, 0); CP_COMMIT();
    stage_copy(1, 1); CP_COMMIT();
    for (int kt = 0; kt < KT; ++kt) {
        CP_WAIT1();                       // stage kt resident (group kt complete)
        __syncthreads();                  // all warps done reading stage (kt-1)%3
        if (kt + 2 < KT) stage_copy((kt + 2) % 3, kt + 2);   // refill freed stage
        CP_COMMIT();                      // unconditional: group arithmetic exact

        const uint32_t so = (kt % 3) * STAGE_BYTES;
        // batch fragment loads for 2 kk-steps (16 back-to-back LDSM), then 64 mmas
        #pragma unroll
        for (int hb = 0; hb < 2; ++hb) {
            const int kk0 = hb * 16, kk1 = hb * 16 + 8;
            uint32_t af0[4][4], af1[4][4], bf0[8][2], bf1[8][2];
            #pragma unroll
            for (int f = 0; f < 4; ++f) ldsm4(af0[f], aAddr[f] + so + kk0 * 4);
            #pragma unroll
            for (int f = 0; f < 4; ++f) ldsm4(af1[f], aAddr[f] + so + kk1 * 4);
            #pragma unroll
            for (int p = 0; p < 4; ++p) {
                uint32_t bq[4];
                ldsm4(bq, bAddr[p] + so + kk0 * 4);
                bf0[2 * p][0] = bq[0]; bf0[2 * p][1] = bq[1];
                bf0[2 * p + 1][0] = bq[2]; bf0[2 * p + 1][1] = bq[3];
            }
            #pragma unroll
            for (int p = 0; p < 4; ++p) {
                uint32_t bq[4];
                ldsm4(bq, bAddr[p] + so + kk1 * 4);
                bf1[2 * p][0] = bq[0]; bf1[2 * p][1] = bq[1];
                bf1[2 * p + 1][0] = bq[2]; bf1[2 * p + 1][1] = bq[3];
            }
            #pragma unroll
            for (int f = 0; f < 4; ++f)
                #pragma unroll
                for (int j = 0; j < 8; ++j)
                    mma8(acc[f][j], af0[f], bf0[j]);
            #pragma unroll
            for (int f = 0; f < 4; ++f)
                #pragma unroll
                for (int j = 0; j < 8; ++j)
                    mma8(acc[f][j], af1[f], bf1[j]);
        }
    }

    // ---------------- epilogue: plain stores (no atomics) ----------------
    const float* Bbias = bias + e * NTOT + n0;
    #pragma unroll
    for (int f = 0; f < 4; ++f) {
        const int rl = mb + f * 16 + g;
        #pragma unroll
        for (int j = 0; j < 8; ++j) {
            const int c = nb + j * 8 + 2 * tg;
            const float b0 = Bbias[c], b1 = Bbias[c + 1];
            float v00 = acc[f][j][0] + b0, v01 = acc[f][j][1] + b1;
            float v10 = acc[f][j][2] + b0, v11 = acc[f][j][3] + b1;
            if (RELU) {
                v00 = fmaxf(v00, 0.f); v01 = fmaxf(v01, 0.f);
                v10 = fmaxf(v10, 0.f); v11 = fmaxf(v11, 0.f);
            }
            if (row0 + rl < cnt) {
                float* p = Y + ((size_t)e * CAP_ + row0 + rl) * NTOT + n0 + c;
                if (TFROUND) { ((uint32_t*)p)[0] = f2tf(v00); ((uint32_t*)p)[1] = f2tf(v01); }
                else         { p[0] = v00; p[1] = v01; }
            }
            if (row0 + rl + 8 < cnt) {
                float* p = Y + ((size_t)e * CAP_ + row0 + rl + 8) * NTOT + n0 + c;
                if (TFROUND) { ((uint32_t*)p)[0] = f2tf(v10); ((uint32_t*)p)[1] = f2tf(v11); }
                else         { p[0] = v10; p[1] = v11; }
            }
        }
    }
}

// ---------------- combine: out[t] = w1*y[p1] + w2*y[p2] ----------------
__global__ void __launch_bounds__(256) combine_kernel(float* __restrict__ out) {
    const int idx = blockIdx.x * blockDim.x + threadIdx.x;    // B_*64 threads
    const int t = idx >> 6, q = idx & 63;
    const int p0 = g_pos[t * 2], p1 = g_pos[t * 2 + 1];
    const float w0 = g_wtk[t * 2], w1 = g_wtk[t * 2 + 1];
    const float4 a = ((const float4*)g_h1)[(size_t)p0 * 64 + q];
    const float4 b = ((const float4*)g_h1)[(size_t)p1 * 64 + q];
    float4 o;
    o.x = w0 * a.x + w1 * b.x;
    o.y = w0 * a.y + w1 * b.y;
    o.z = w0 * a.z + w1 * b.z;
    o.w = w0 * a.w + w1 * b.w;
    ((float4*)out)[(size_t)t * 64 + q] = o;
}

// ---------------- aux outputs ----------------
__global__ void finalize_kernel(float* __restrict__ out) {
    __shared__ float us[E_];
    const int e = threadIdx.x;
    if (e < E_) {
        float u = (float)g_counts[e] / (float)B_;
        us[e] = u;
        out[(size_t)B_ * D_OUT_ + 1 + e] = u;
    }
    __syncthreads();
    if (e == 0) {
        float s = 0.f;
        #pragma unroll
        for (int i = 0; i < E_; ++i) { float d = us[i] - (1.f / E_); s += d * d; }
        out[(size_t)B_ * D_OUT_] = (s / E_) * 0.01f;
    }
}

// ---------------- launch (gemm2 at slot 4 for ncu capture) ----------------
extern "C" void kernel_launch(void* const* d_in, const int* in_sizes, int n_in,
                              void* d_out, int out_size) {
    const float* x   = (const float*)d_in[0];
    const float* gW1 = (const float*)d_in[1];
    const float* gb1 = (const float*)d_in[2];
    const float* gW2 = (const float*)d_in[3];
    const float* gb2 = (const float*)d_in[4];
    const float* We1 = (const float*)d_in[5];
    const float* be1 = (const float*)d_in[6];
    const float* We2 = (const float*)d_in[7];
    const float* be2 = (const float*)d_in[8];
    const float* We3 = (const float*)d_in[9];
    const float* be3 = (const float*)d_in[10];
    float* out = (float*)d_out;

    cudaFuncSetAttribute(gating_kernel, cudaFuncAttributeMaxDynamicSharedMemorySize,
                         GATE_DSMEM);
    cudaFuncSetAttribute(gemm_mma<256, 512, 1, true,  true>,
                         cudaFuncAttributeMaxDynamicSharedMemorySize, GEMM_DSMEM);
    cudaFuncSetAttribute(gemm_mma<512, 512, 2, true,  true>,
                         cudaFuncAttributeMaxDynamicSharedMemorySize, GEMM_DSMEM);
    cudaFuncSetAttribute(gemm_mma<512, 256, 3, false, false>,
                         cudaFuncAttributeMaxDynamicSharedMemorySize, GEMM_DSMEM);

    transpose_all<<<dim3(16, 16, 24), 256>>>(We1, We2, We3);            // 1 (+ zero counts)
    gating_kernel<<<256, 256, GATE_DSMEM>>>(x, gW1, gb1, gW2, gb2);     // 2
    gemm_mma<256, 512, 1, true,  true ><<<dim3(2, CAP_ / 128, E_), 256, GEMM_DSMEM>>>(be1, x);       // 3
    gemm_mma<512, 512, 2, true,  true ><<<dim3(2, CAP_ / 128, E_), 256, GEMM_DSMEM>>>(be2, nullptr); // 4 <- profiled
    gemm_mma<512, 256, 3, false, false><<<dim3(1, CAP_ / 128, E_), 256, GEMM_DSMEM>>>(be3, nullptr); // 5
    combine_kernel<<<B_ * 64 / 256, 256>>>(out);                        // 6
    finalize_kernel<<<1, 32>>>(out);                                    // 7
}

// round 16
// speedup vs baseline: 1.0534x; 1.0534x over previous
#include <cuda_runtime.h>
#include <stdint.h>
#include <math.h>

#define B_     32768
#define D_IN_  256
#define D_OUT_ 256
#define E_     8
#define H_     512
#define GH_    128
#define CAP_   32768

// ---------------- scratch (static __device__, no allocation) ----------------
__device__ int   g_counts[E_];
__device__ int   g_list[E_ * B_];
__device__ int   g_pos[B_ * 2];                     // token -> (e*CAP+row) x2
__device__ float g_wtk[B_ * 2];                     // token -> combine weights x2
__device__ float g_h1[(size_t)E_ * CAP_ * H_];      // layer-1 acts; reused as y3 [.][256]
__device__ float g_h2[(size_t)E_ * CAP_ * H_];      // layer-2 acts
__device__ float g_wT1[(size_t)E_ * H_ * D_IN_];    // We1^T tf32
__device__ float g_wT2[(size_t)E_ * H_ * H_];       // We2^T tf32
__device__ float g_wT3[(size_t)E_ * D_OUT_ * H_];   // We3^T tf32

// ---------------- helpers ----------------
__device__ __forceinline__ uint32_t smem_u32(const void* p) {
    uint32_t a;
    asm("{ .reg .u64 t; cvta.to.shared.u64 t, %1; cvt.u32.u64 %0, t; }" : "=r"(a) : "l"(p));
    return a;
}
__device__ __forceinline__ uint32_t f2tf(float x) {
    uint32_t u;
    asm("cvt.rna.tf32.f32 %0, %1;" : "=r"(u) : "f"(x));
    return u;
}
__device__ __forceinline__ void cp16(uint32_t dst, const float* src) {
    asm volatile("cp.async.cg.shared.global [%0], [%1], 16;"
                 :: "r"(dst), "l"(__cvta_generic_to_global(src)) : "memory");
}
#define CP_COMMIT() asm volatile("cp.async.commit_group;" ::: "memory")
#define CP_WAIT1()  asm volatile("cp.async.wait_group 1;" ::: "memory")

__device__ __forceinline__ void ldsm4(uint32_t* r, uint32_t a) {
    asm volatile("ldmatrix.sync.aligned.m8n8.x4.shared.b16 {%0,%1,%2,%3}, [%4];"
                 : "=r"(r[0]), "=r"(r[1]), "=r"(r[2]), "=r"(r[3]) : "r"(a));
}
__device__ __forceinline__ void mma8(float* d, const uint32_t* a, const uint32_t* b) {
    asm volatile(
        "mma.sync.aligned.m16n8k8.row.col.f32.tf32.tf32.f32 "
        "{%0,%1,%2,%3},{%4,%5,%6,%7},{%8,%9},{%0,%1,%2,%3};\n"
        : "+f"(d[0]), "+f"(d[1]), "+f"(d[2]), "+f"(d[3])
        : "r"(a[0]), "r"(a[1]), "r"(a[2]), "r"(a[3]), "r"(b[0]), "r"(b[1]));
}

// ---------------- one-shot: all 3 weight transposes (tf32 round) + counter zero ----------------
__global__ void __launch_bounds__(256) transpose_all(
    const float* __restrict__ We1, const float* __restrict__ We2,
    const float* __restrict__ We3)
{
    __shared__ float t[32][33];
    const int sel = blockIdx.z >> 3, e = blockIdx.z & 7;
    const int K = (sel == 0) ? 256 : 512;
    const int N = (sel == 2) ? 256 : 512;
    if (blockIdx.x * 32 >= K || blockIdx.y * 32 >= N) return;
    if (blockIdx.x == 0 && blockIdx.y == 0 && blockIdx.z == 0 && threadIdx.x < E_)
        g_counts[threadIdx.x] = 0;
    const float* I = ((sel == 0) ? We1 : (sel == 1) ? We2 : We3) + (size_t)e * K * N;
    float* O = ((sel == 0) ? g_wT1 : (sel == 1) ? g_wT2 : g_wT3) + (size_t)e * K * N;
    const int k0 = blockIdx.x * 32, n0 = blockIdx.y * 32;
    const int tx = threadIdx.x & 31, ty = threadIdx.x >> 5;
    #pragma unroll
    for (int p = 0; p < 32; p += 8)
        t[ty + p][tx] = I[(size_t)(k0 + ty + p) * N + n0 + tx];
    __syncthreads();
    #pragma unroll
    for (int p = 0; p < 32; p += 8)
        O[(size_t)(n0 + ty + p) * K + k0 + tx] = __uint_as_float(f2tf(t[tx][ty + p]));
}

// ---------------- gating: register-tiled fp32 SGEMM (proven r11), routing bit-identical ----------------
#define GATE_DSMEM (128 * 132 * 4)
__global__ void __launch_bounds__(256, 2) gating_kernel(
    const float* __restrict__ x,  const float* __restrict__ gW1,
    const float* __restrict__ gb1, const float* __restrict__ gW2,
    const float* __restrict__ gb2)
{
    extern __shared__ float dsm[];            // staging As[8][132]+Bs[8][132]; later h[128][132]
    float* As = dsm;
    float* Bs = dsm + 8 * 132;
    __shared__ float b1s[GH_], w2s[GH_ * E_], b2s[E_], logt[128 * E_];

    const int tid = threadIdx.x;
    const int tok0 = blockIdx.x * 128;
    if (tid < GH_) b1s[tid] = gb1[tid];
    for (int i = tid; i < GH_ * E_; i += 256) w2s[i] = gW2[i];
    if (tid < E_) b2s[tid] = gb2[tid];

    const int m_ld = tid & 127, half = tid >> 7;
    const int kb_ld = tid >> 5, j_ld = (tid & 31) * 4;
    const int tx = tid & 15, ty = tid >> 4;
    const int ma = ty * 4, jb = tx * 4;

    float acc[8][8];
    #pragma unroll
    for (int i = 0; i < 8; ++i)
        #pragma unroll
        for (int j = 0; j < 8; ++j) acc[i][j] = 0.f;

    for (int kt = 0; kt < 32; ++kt) {
        const int k0 = kt * 8;
        float4 xa = *(const float4*)(x + (size_t)(tok0 + m_ld) * D_IN_ + k0 + half * 4);
        float4 wb = *(const float4*)(gW1 + (size_t)(k0 + kb_ld) * GH_ + j_ld);
        __syncthreads();
        As[(half * 4 + 0) * 132 + m_ld] = xa.x;
        As[(half * 4 + 1) * 132 + m_ld] = xa.y;
        As[(half * 4 + 2) * 132 + m_ld] = xa.z;
        As[(half * 4 + 3) * 132 + m_ld] = xa.w;
        *(float4*)(Bs + kb_ld * 132 + j_ld) = wb;
        __syncthreads();

        #pragma unroll
        for (int g = 0; g < 2; ++g) {
            #pragma unroll
            for (int kk = 3; kk >= 0; --kk) {
                const int k = g * 4 + kk;
                float4 a0 = *(const float4*)(As + k * 132 + ma);
                float4 a1 = *(const float4*)(As + k * 132 + 64 + ma);
                float4 b0 = *(const float4*)(Bs + k * 132 + jb);
                float4 b1 = *(const float4*)(Bs + k * 132 + 64 + jb);
                const float av[8] = {a0.x, a0.y, a0.z, a0.w, a1.x, a1.y, a1.z, a1.w};
                const float bv[8] = {b0.x, b0.y, b0.z, b0.w, b1.x, b1.y, b1.z, b1.w};
                #pragma unroll
                for (int i = 0; i < 8; ++i)
                    #pragma unroll
                    for (int j = 0; j < 8; ++j)
                        acc[i][j] = fmaf(av[i], bv[j], acc[i][j]);
            }
        }
    }
    __syncthreads();

    float* hsm = dsm;
    #pragma unroll
    for (int i = 0; i < 8; ++i) {
        const int m = ma + (i & 3) + (i >> 2) * 64;
        #pragma unroll
        for (int j = 0; j < 8; ++j) {
            const int jj = jb + (j & 3) + (j >> 2) * 64;
            hsm[m * 132 + jj] = fmaxf(acc[i][j] + b1s[jj], 0.f);
        }
    }
    __syncthreads();

    #pragma unroll
    for (int q = 0; q < 4; ++q) {
        const int pid = tid + q * 256;
        const int tok = pid >> 3, ee = pid & 7;
        float a = b2s[ee];
        const float* hrow = hsm + tok * 132;
        #pragma unroll 8
        for (int h = 0; h < 128; ++h) a = fmaf(hrow[h], w2s[h * 8 + ee], a);
        logt[tok * 8 + ee] = a;
    }
    __syncthreads();

    if (tid < 128) {
        float l[8];
        #pragma unroll
        for (int q = 0; q < 8; ++q) l[q] = logt[tid * 8 + q];
        int i1 = 0; float m1 = l[0];
        #pragma unroll
        for (int q = 1; q < 8; ++q) if (l[q] > m1) { m1 = l[q]; i1 = q; }
        int i2 = -1; float m2 = -1e30f;
        #pragma unroll
        for (int q = 0; q < 8; ++q) if (q != i1 && l[q] > m2) { m2 = l[q]; i2 = q; }
        const int t = tok0 + tid;
        const float ex  = expf(m2 - m1);
        const float den = 1.f + ex;
        int p1 = atomicAdd(&g_counts[i1], 1);
        g_list[i1 * B_ + p1] = t;
        int p2 = atomicAdd(&g_counts[i2], 1);
        g_list[i2 * B_ + p2] = t;
        g_pos[t * 2]     = i1 * CAP_ + p1;
        g_pos[t * 2 + 1] = i2 * CAP_ + p2;
        g_wtk[t * 2]     = 1.f / den;
        g_wtk[t * 2 + 1] = ex / den;
    }
}

// ---------------- tf32 mma.sync GEMM: 128x128, 2x2 warps of 64x64 (sacred tile),
// BK=16, 3-stage ring, 3 CTAs/SM (smem 61.4KB, regs capped via launch_bounds) ----------------
#define AP 20                         // row stride (floats): 16B aligned, ldmatrix conflict-free
#define A_STG_B     10240             // 128*20*4
#define STAGE_BYTES 20480             // A + B (128*20*4 each)
#define GEMM_DSMEM  61440             // 3 stages

template<int K, int NTOT, int STAGE, bool RELU, bool TFROUND>
__global__ void __launch_bounds__(128, 3) gemm_mma(const float* __restrict__ bias,
                                                   const float* __restrict__ xsrc)
{
    const int e = blockIdx.z;
    const int cnt = g_counts[e];
    const int row0 = blockIdx.y * 128;     // y = row tile
    if (row0 >= cnt) return;
    const int n0 = blockIdx.x * 128;       // x = n tile (fast-varying -> A L2 reuse)

    extern __shared__ float dsm[];
    const uint32_t smBase = smem_u32(dsm);
    __shared__ int stok[128];

    const int tid = threadIdx.x;
    const int lid = tid & 31, wid = tid >> 5;
    const int g = lid >> 2, tg = lid & 3;
    const int wm = wid >> 1, wn = wid & 1;
    const int mb = wm * 64,  nb = wn * 64;

    const float* A  = (STAGE == 1) ? xsrc  : (STAGE == 2) ? g_h1 : g_h2;
    const float* Wt = (STAGE == 1) ? g_wT1 : (STAGE == 2) ? g_wT2 : g_wT3;
    float* Y = (STAGE == 1) ? g_h1 : (STAGE == 2) ? g_h2 : g_h1;   // stage3: y rows [.][256]
    const float* Ab = A + ((STAGE == 1) ? 0 : ((size_t)e * CAP_ + row0) * K);
    const float* Bb = Wt + ((size_t)e * NTOT + n0) * K;

    if (STAGE == 1) {   // index table: tile row -> token row of x
        int r = row0 + tid;
        stok[tid] = (r < cnt) ? g_list[e * B_ + r] : 0;
        __syncthreads();
    }

    const int lane_row = (lid & 7) + (((lid >> 3) & 1) << 3);
    const int lane_k   = (lid >> 4) * 4;
    uint32_t aAddr[4], bAddr[4];
    #pragma unroll
    for (int f = 0; f < 4; ++f)
        aAddr[f] = smBase + ((mb + f * 16 + lane_row) * AP + lane_k) * 4;
    {
        const int grp = lid >> 3;
        #pragma unroll
        for (int p = 0; p < 4; ++p) {
            const int n_loc = nb + (2 * p + (grp >> 1)) * 8 + (lid & 7);
            const int kcol  = (grp & 1) * 4;
            bAddr[p] = smBase + A_STG_B + (n_loc * AP + kcol) * 4;
        }
    }

    float acc[4][8][4];
    #pragma unroll
    for (int f = 0; f < 4; ++f)
        #pragma unroll
        for (int j = 0; j < 8; ++j)
            #pragma unroll
            for (int q = 0; q < 4; ++q) acc[f][j][q] = 0.f;

    // staging per tile: A 512 float4 (4/thread) + B 512 float4 (4/thread)
    auto stage_copy = [&](int buf, int kt) {
        const uint32_t sb = smBase + buf * STAGE_BYTES;
        const int k0 = kt * 16;
        #pragma unroll
        for (int q = 0; q < 4; ++q) {
            const int c = q * 128 + tid;
            const int r = c >> 2, gg = (c & 3) * 4;
            const uint32_t doff = (r * AP + gg) * 4;
            const float* srcA = (STAGE == 1)
                ? Ab + (size_t)stok[r] * K + k0 + gg
                : Ab + (size_t)r * K + k0 + gg;
            cp16(sb + doff,           srcA);
            cp16(sb + A_STG_B + doff, Bb + (size_t)r * K + k0 + gg);
        }
    };

    constexpr int KT = K / 16;
    stage_copy(0, 0); CP_COMMIT();
    stage_copy(1, 1); CP_COMMIT();
    for (int kt = 0; kt < KT; ++kt) {
        CP_WAIT1();                       // stage kt resident (group kt complete)
        __syncthreads();                  // all warps done reading stage (kt-1)%3
        if (kt + 2 < KT) stage_copy((kt + 2) % 3, kt + 2);   // refill freed stage
        CP_COMMIT();                      // unconditional: group arithmetic exact

        const uint32_t so = (kt % 3) * STAGE_BYTES;
        #pragma unroll
        for (int kk = 0; kk < 16; kk += 8) {
            uint32_t af[4][4], bf[8][2];
            #pragma unroll
            for (int f = 0; f < 4; ++f) ldsm4(af[f], aAddr[f] + so + kk * 4);
            #pragma unroll
            for (int p = 0; p < 4; ++p) {
                uint32_t bq[4];
                ldsm4(bq, bAddr[p] + so + kk * 4);
                bf[2 * p][0] = bq[0]; bf[2 * p][1] = bq[1];
                bf[2 * p + 1][0] = bq[2]; bf[2 * p + 1][1] = bq[3];
            }
            #pragma unroll
            for (int f = 0; f < 4; ++f)
                #pragma unroll
                for (int j = 0; j < 8; ++j)
                    mma8(acc[f][j], af[f], bf[j]);
        }
    }

    // ---------------- epilogue: plain stores (no atomics) ----------------
    const float* Bbias = bias + e * NTOT + n0;
    #pragma unroll
    for (int f = 0; f < 4; ++f) {
        const int rl = mb + f * 16 + g;
        #pragma unroll
        for (int j = 0; j < 8; ++j) {
            const int c = nb + j * 8 + 2 * tg;
            const float b0 = Bbias[c], b1 = Bbias[c + 1];
            float v00 = acc[f][j][0] + b0, v01 = acc[f][j][1] + b1;
            float v10 = acc[f][j][2] + b0, v11 = acc[f][j][3] + b1;
            if (RELU) {
                v00 = fmaxf(v00, 0.f); v01 = fmaxf(v01, 0.f);
                v10 = fmaxf(v10, 0.f); v11 = fmaxf(v11, 0.f);
            }
            if (row0 + rl < cnt) {
                float* p = Y + ((size_t)e * CAP_ + row0 + rl) * NTOT + n0 + c;
                if (TFROUND) { ((uint32_t*)p)[0] = f2tf(v00); ((uint32_t*)p)[1] = f2tf(v01); }
                else         { p[0] = v00; p[1] = v01; }
            }
            if (row0 + rl + 8 < cnt) {
                float* p = Y + ((size_t)e * CAP_ + row0 + rl + 8) * NTOT + n0 + c;
                if (TFROUND) { ((uint32_t*)p)[0] = f2tf(v10); ((uint32_t*)p)[1] = f2tf(v11); }
                else         { p[0] = v10; p[1] = v11; }
            }
        }
    }
}

// ---------------- combine (+ finalize in block 0): out[t] = w1*y[p1] + w2*y[p2] ----------------
__global__ void __launch_bounds__(256) combine_kernel(float* __restrict__ out) {
    const int idx = blockIdx.x * blockDim.x + threadIdx.x;    // B_*64 threads
    const int t = idx >> 6, q = idx & 63;
    const int p0 = g_pos[t * 2], p1 = g_pos[t * 2 + 1];
    const float w0 = g_wtk[t * 2], w1 = g_wtk[t * 2 + 1];
    const float4 a = ((const float4*)g_h1)[(size_t)p0 * 64 + q];
    const float4 b = ((const float4*)g_h1)[(size_t)p1 * 64 + q];
    float4 o;
    o.x = w0 * a.x + w1 * b.x;
    o.y = w0 * a.y + w1 * b.y;
    o.z = w0 * a.z + w1 * b.z;
    o.w = w0 * a.w + w1 * b.w;
    ((float4*)out)[(size_t)t * 64 + q] = o;

    // aux outputs (counts fixed since gating; independent of combine data)
    if (blockIdx.x == 0 && threadIdx.x == 0) {
        float us[E_];
        #pragma unroll
        for (int e2 = 0; e2 < E_; ++e2) {
            us[e2] = (float)g_counts[e2] / (float)B_;
            out[(size_t)B_ * D_OUT_ + 1 + e2] = us[e2];
        }
        float s = 0.f;
        #pragma unroll
        for (int i = 0; i < E_; ++i) { float d = us[i] - (1.f / E_); s += d * d; }
        out[(size_t)B_ * D_OUT_] = (s / E_) * 0.01f;
    }
}

// ---------------- launch (gemm2 at slot 4 for ncu capture) ----------------
extern "C" void kernel_launch(void* const* d_in, const int* in_sizes, int n_in,
                              void* d_out, int out_size) {
    const float* x   = (const float*)d_in[0];
    const float* gW1 = (const float*)d_in[1];
    const float* gb1 = (const float*)d_in[2];
    const float* gW2 = (const float*)d_in[3];
    const float* gb2 = (const float*)d_in[4];
    const float* We1 = (const float*)d_in[5];
    const float* be1 = (const float*)d_in[6];
    const float* We2 = (const float*)d_in[7];
    const float* be2 = (const float*)d_in[8];
    const float* We3 = (const float*)d_in[9];
    const float* be3 = (const float*)d_in[10];
    float* out = (float*)d_out;

    cudaFuncSetAttribute(gating_kernel, cudaFuncAttributeMaxDynamicSharedMemorySize,
                         GATE_DSMEM);
    cudaFuncSetAttribute(gemm_mma<256, 512, 1, true,  true>,
                         cudaFuncAttributeMaxDynamicSharedMemorySize, GEMM_DSMEM);
    cudaFuncSetAttribute(gemm_mma<512, 512, 2, true,  true>,
                         cudaFuncAttributeMaxDynamicSharedMemorySize, GEMM_DSMEM);
    cudaFuncSetAttribute(gemm_mma<512, 256, 3, false, false>,
                         cudaFuncAttributeMaxDynamicSharedMemorySize, GEMM_DSMEM);

    transpose_all<<<dim3(16, 16, 24), 256>>>(We1, We2, We3);            // 1 (+ zero counts)
    gating_kernel<<<256, 256, GATE_DSMEM>>>(x, gW1, gb1, gW2, gb2);     // 2
    gemm_mma<256, 512, 1, true,  true ><<<dim3(4, CAP_ / 128, E_), 128, GEMM_DSMEM>>>(be1, x);       // 3
    gemm_mma<512, 512, 2, true,  true ><<<dim3(4, CAP_ / 128, E_), 128, GEMM_DSMEM>>>(be2, nullptr); // 4 <- profiled
    gemm_mma<512, 256, 3, false, false><<<dim3(2, CAP_ / 128, E_), 128, GEMM_DSMEM>>>(be3, nullptr); // 5
    combine_kernel<<<B_ * 64 / 256, 256>>>(out);                        // 6 (+ finalize)
}

// round 17
// speedup vs baseline: 1.6487x; 1.5651x over previous
#include <cuda_runtime.h>
#include <cuda_fp16.h>
#include <stdint.h>
#include <math.h>

#define B_     32768
#define D_IN_  256
#define D_OUT_ 256
#define E_     8
#define H_     512
#define GH_    128
#define CAP_   32768

// ---------------- scratch (static __device__, no allocation) ----------------
__device__ int    g_counts[E_];
__device__ int    g_list[E_ * B_];
__device__ int    g_pos[B_ * 2];                      // token -> (e*CAP+row) x2
__device__ float  g_wtk[B_ * 2];                      // token -> combine weights x2
__device__ __half g_x16[(size_t)E_ * CAP_ * D_IN_];   // gathered inputs fp16
__device__ __half g_h1h[(size_t)E_ * CAP_ * H_];      // layer-1 acts fp16
__device__ __half g_h2h[(size_t)E_ * CAP_ * H_];      // layer-2 acts fp16
__device__ float  g_y[(size_t)E_ * CAP_ * D_OUT_];    // layer-3 out fp32
__device__ __half g_w1h[(size_t)E_ * H_ * D_IN_];     // We1^T fp16 [E][512][256]
__device__ __half g_w2h[(size_t)E_ * H_ * H_];        // We2^T fp16
__device__ __half g_w3h[(size_t)E_ * D_OUT_ * H_];    // We3^T fp16

// ---------------- helpers ----------------
__device__ __forceinline__ uint32_t smem_u32(const void* p) {
    uint32_t a;
    asm("{ .reg .u64 t; cvta.to.shared.u64 t, %1; cvt.u32.u64 %0, t; }" : "=r"(a) : "l"(p));
    return a;
}
__device__ __forceinline__ void cp16(uint32_t dst, const void* src) {
    asm volatile("cp.async.cg.shared.global [%0], [%1], 16;"
                 :: "r"(dst), "l"(__cvta_generic_to_global(src)) : "memory");
}
#define CP_COMMIT() asm volatile("cp.async.commit_group;" ::: "memory")
#define CP_WAIT1()  asm volatile("cp.async.wait_group 1;" ::: "memory")

__device__ __forceinline__ void ldsm4(uint32_t* r, uint32_t a) {
    asm volatile("ldmatrix.sync.aligned.m8n8.x4.shared.b16 {%0,%1,%2,%3}, [%4];"
                 : "=r"(r[0]), "=r"(r[1]), "=r"(r[2]), "=r"(r[3]) : "r"(a));
}
__device__ __forceinline__ void mma16(float* d, const uint32_t* a, const uint32_t* b) {
    asm volatile(
        "mma.sync.aligned.m16n8k16.row.col.f32.f16.f16.f32 "
        "{%0,%1,%2,%3},{%4,%5,%6,%7},{%8,%9},{%0,%1,%2,%3};\n"
        : "+f"(d[0]), "+f"(d[1]), "+f"(d[2]), "+f"(d[3])
        : "r"(a[0]), "r"(a[1]), "r"(a[2]), "r"(a[3]), "r"(b[0]), "r"(b[1]));
}

// ---------------- one-shot: all 3 weight transposes (-> fp16) + counter zero ----------------
__global__ void __launch_bounds__(256) transpose_all(
    const float* __restrict__ We1, const float* __restrict__ We2,
    const float* __restrict__ We3)
{
    __shared__ float t[32][33];
    const int sel = blockIdx.z >> 3, e = blockIdx.z & 7;
    const int K = (sel == 0) ? 256 : 512;
    const int N = (sel == 2) ? 256 : 512;
    if (blockIdx.x * 32 >= K || blockIdx.y * 32 >= N) return;
    if (blockIdx.x == 0 && blockIdx.y == 0 && blockIdx.z == 0 && threadIdx.x < E_)
        g_counts[threadIdx.x] = 0;
    const float* I = ((sel == 0) ? We1 : (sel == 1) ? We2 : We3) + (size_t)e * K * N;
    __half* O = ((sel == 0) ? g_w1h : (sel == 1) ? g_w2h : g_w3h) + (size_t)e * K * N;
    const int k0 = blockIdx.x * 32, n0 = blockIdx.y * 32;
    const int tx = threadIdx.x & 31, ty = threadIdx.x >> 5;
    #pragma unroll
    for (int p = 0; p < 32; p += 8)
        t[ty + p][tx] = I[(size_t)(k0 + ty + p) * N + n0 + tx];
    __syncthreads();
    #pragma unroll
    for (int p = 0; p < 32; p += 8)
        O[(size_t)(n0 + ty + p) * K + k0 + tx] = __float2half_rn(t[tx][ty + p]);
}

// ---------------- gating: register-tiled fp32 SGEMM (proven r11), routing bit-identical ----------------
#define GATE_DSMEM (128 * 132 * 4)
__global__ void __launch_bounds__(256, 2) gating_kernel(
    const float* __restrict__ x,  const float* __restrict__ gW1,
    const float* __restrict__ gb1, const float* __restrict__ gW2,
    const float* __restrict__ gb2)
{
    extern __shared__ float dsm[];
    float* As = dsm;
    float* Bs = dsm + 8 * 132;
    __shared__ float b1s[GH_], w2s[GH_ * E_], b2s[E_], logt[128 * E_];

    const int tid = threadIdx.x;
    const int tok0 = blockIdx.x * 128;
    if (tid < GH_) b1s[tid] = gb1[tid];
    for (int i = tid; i < GH_ * E_; i += 256) w2s[i] = gW2[i];
    if (tid < E_) b2s[tid] = gb2[tid];

    const int m_ld = tid & 127, half = tid >> 7;
    const int kb_ld = tid >> 5, j_ld = (tid & 31) * 4;
    const int tx = tid & 15, ty = tid >> 4;
    const int ma = ty * 4, jb = tx * 4;

    float acc[8][8];
    #pragma unroll
    for (int i = 0; i < 8; ++i)
        #pragma unroll
        for (int j = 0; j < 8; ++j) acc[i][j] = 0.f;

    for (int kt = 0; kt < 32; ++kt) {
        const int k0 = kt * 8;
        float4 xa = *(const float4*)(x + (size_t)(tok0 + m_ld) * D_IN_ + k0 + half * 4);
        float4 wb = *(const float4*)(gW1 + (size_t)(k0 + kb_ld) * GH_ + j_ld);
        __syncthreads();
        As[(half * 4 + 0) * 132 + m_ld] = xa.x;
        As[(half * 4 + 1) * 132 + m_ld] = xa.y;
        As[(half * 4 + 2) * 132 + m_ld] = xa.z;
        As[(half * 4 + 3) * 132 + m_ld] = xa.w;
        *(float4*)(Bs + kb_ld * 132 + j_ld) = wb;
        __syncthreads();

        #pragma unroll
        for (int g = 0; g < 2; ++g) {
            #pragma unroll
            for (int kk = 3; kk >= 0; --kk) {
                const int k = g * 4 + kk;
                float4 a0 = *(const float4*)(As + k * 132 + ma);
                float4 a1 = *(const float4*)(As + k * 132 + 64 + ma);
                float4 b0 = *(const float4*)(Bs + k * 132 + jb);
                float4 b1 = *(const float4*)(Bs + k * 132 + 64 + jb);
                const float av[8] = {a0.x, a0.y, a0.z, a0.w, a1.x, a1.y, a1.z, a1.w};
                const float bv[8] = {b0.x, b0.y, b0.z, b0.w, b1.x, b1.y, b1.z, b1.w};
                #pragma unroll
                for (int i = 0; i < 8; ++i)
                    #pragma unroll
                    for (int j = 0; j < 8; ++j)
                        acc[i][j] = fmaf(av[i], bv[j], acc[i][j]);
            }
        }
    }
    __syncthreads();

    float* hsm = dsm;
    #pragma unroll
    for (int i = 0; i < 8; ++i) {
        const int m = ma + (i & 3) + (i >> 2) * 64;
        #pragma unroll
        for (int j = 0; j < 8; ++j) {
            const int jj = jb + (j & 3) + (j >> 2) * 64;
            hsm[m * 132 + jj] = fmaxf(acc[i][j] + b1s[jj], 0.f);
        }
    }
    __syncthreads();

    #pragma unroll
    for (int q = 0; q < 4; ++q) {
        const int pid = tid + q * 256;
        const int tok = pid >> 3, ee = pid & 7;
        float a = b2s[ee];
        const float* hrow = hsm + tok * 132;
        #pragma unroll 8
        for (int h = 0; h < 128; ++h) a = fmaf(hrow[h], w2s[h * 8 + ee], a);
        logt[tok * 8 + ee] = a;
    }
    __syncthreads();

    if (tid < 128) {
        float l[8];
        #pragma unroll
        for (int q = 0; q < 8; ++q) l[q] = logt[tid * 8 + q];
        int i1 = 0; float m1 = l[0];
        #pragma unroll
        for (int q = 1; q < 8; ++q) if (l[q] > m1) { m1 = l[q]; i1 = q; }
        int i2 = -1; float m2 = -1e30f;
        #pragma unroll
        for (int q = 0; q < 8; ++q) if (q != i1 && l[q] > m2) { m2 = l[q]; i2 = q; }
        const int t = tok0 + tid;
        const float ex  = expf(m2 - m1);
        const float den = 1.f + ex;
        int p1 = atomicAdd(&g_counts[i1], 1);
        g_list[i1 * B_ + p1] = t;
        int p2 = atomicAdd(&g_counts[i2], 1);
        g_list[i2 * B_ + p2] = t;
        g_pos[t * 2]     = i1 * CAP_ + p1;
        g_pos[t * 2 + 1] = i2 * CAP_ + p2;
        g_wtk[t * 2]     = 1.f / den;
        g_wtk[t * 2 + 1] = ex / den;
    }
}

// ---------------- gather x rows -> per-expert fp16 segments ----------------
__global__ void __launch_bounds__(256) gather_kernel(const float* __restrict__ x) {
    const int e = blockIdx.y;
    const int n = g_counts[e];
    const int row0 = blockIdx.x * 64;
    if (row0 >= n) return;
    for (int v = threadIdx.x; v < 64 * 32; v += 256) {
        int r = row0 + (v >> 5);
        if (r < n) {
            int t = g_list[e * B_ + r];
            const float4* src = (const float4*)(x + (size_t)t * D_IN_) + (v & 31) * 2;
            float4 s0 = src[0], s1 = src[1];
            __half2 h[4];
            h[0] = __floats2half2_rn(s0.x, s0.y);
            h[1] = __floats2half2_rn(s0.z, s0.w);
            h[2] = __floats2half2_rn(s1.x, s1.y);
            h[3] = __floats2half2_rn(s1.z, s1.w);
            *(uint4*)(g_x16 + ((size_t)e * CAP_ + r) * D_IN_ + (v & 31) * 8) = *(uint4*)h;
        }
    }
}

// ---------------- fp16 mma.sync GEMM: 128x128, 2x2 warps of 64x64, BK=32 halves, 3 stages ----------------
#define APH 40                        // smem row stride in halves (80B: aligned + conflict-free)
#define A_STG_B     10240             // 128*40*2
#define STAGE_BYTES 20480             // A + B
#define GEMM_DSMEM  61440             // 3 stages

template<int K, int NTOT, int STAGE, bool RELU>
__global__ void __launch_bounds__(128) gemm_mma(const float* __restrict__ bias)
{
    const int e = blockIdx.z;
    const int cnt = g_counts[e];
    const int row0 = blockIdx.y * 128;     // y = row tile
    if (row0 >= cnt) return;
    const int n0 = blockIdx.x * 128;       // x = n tile (fast-varying -> A L2 reuse)

    extern __shared__ char dsmc[];
    const uint32_t smBase = smem_u32(dsmc);

    const int tid = threadIdx.x;
    const int lid = tid & 31, wid = tid >> 5;
    const int g = lid >> 2, tg = lid & 3;
    const int wm = wid >> 1, wn = wid & 1;
    const int mb = wm * 64,  nb = wn * 64;

    const __half* A  = (STAGE == 1) ? g_x16 : (STAGE == 2) ? g_h1h : g_h2h;
    const __half* Wt = (STAGE == 1) ? g_w1h : (STAGE == 2) ? g_w2h : g_w3h;
    const __half* Ab = A  + ((size_t)e * CAP_ + row0) * K;
    const __half* Bb = Wt + ((size_t)e * NTOT + n0) * K;

    // ldmatrix per-lane addresses (byte offsets within a stage)
    const int lane_row = (lid & 7) + (((lid >> 3) & 1) << 3);   // 0..15
    const int lane_kb  = (lid >> 4) * 16;                       // byte offset 0 or 16
    uint32_t aAddr[4], bAddr[4];
    #pragma unroll
    for (int f = 0; f < 4; ++f)
        aAddr[f] = smBase + (mb + f * 16 + lane_row) * (APH * 2) + lane_kb;
    {
        const int grp = lid >> 3;
        #pragma unroll
        for (int p = 0; p < 4; ++p) {
            const int n_loc = nb + (2 * p + (grp >> 1)) * 8 + (lid & 7);
            bAddr[p] = smBase + A_STG_B + n_loc * (APH * 2) + (grp & 1) * 16;
        }
    }

    float acc[4][8][4];
    #pragma unroll
    for (int f = 0; f < 4; ++f)
        #pragma unroll
        for (int j = 0; j < 8; ++j)
            #pragma unroll
            for (int q = 0; q < 4; ++q) acc[f][j][q] = 0.f;

    // staging per tile: A 128 rows x 64B = 512 chunks (4/thread); B same
    auto stage_copy = [&](int buf, int kt) {
        const uint32_t sb = smBase + buf * STAGE_BYTES;
        const int k0 = kt * 32;
        #pragma unroll
        for (int q = 0; q < 4; ++q) {
            const int c = q * 128 + tid;
            const int r = c >> 2, gg = (c & 3) * 8;         // gg in halves
            const uint32_t doff = r * (APH * 2) + gg * 2;
            cp16(sb + doff,           Ab + (size_t)r * K + k0 + gg);
            cp16(sb + A_STG_B + doff, Bb + (size_t)r * K + k0 + gg);
        }
    };

    constexpr int KT = K / 32;
    stage_copy(0, 0); CP_COMMIT();
    stage_copy(1, 1); CP_COMMIT();
    for (int kt = 0; kt < KT; ++kt) {
        CP_WAIT1();                       // stage kt resident (group kt complete)
        __syncthreads();                  // all warps done reading stage (kt-1)%3
        if (kt + 2 < KT) stage_copy((kt + 2) % 3, kt + 2);   // refill freed stage
        CP_COMMIT();                      // unconditional: group arithmetic exact

        const uint32_t so = (kt % 3) * STAGE_BYTES;
        #pragma unroll
        for (int kk = 0; kk < 2; ++kk) {  // two k16 steps per 32-half tile
            const uint32_t ko = so + kk * 32;   // 16 halves = 32 bytes
            uint32_t af[4][4], bf[8][2];
            #pragma unroll
            for (int f = 0; f < 4; ++f) ldsm4(af[f], aAddr[f] + ko);
            #pragma unroll
            for (int p = 0; p < 4; ++p) {
                uint32_t bq[4];
                ldsm4(bq, bAddr[p] + ko);
                bf[2 * p][0] = bq[0]; bf[2 * p][1] = bq[1];
                bf[2 * p + 1][0] = bq[2]; bf[2 * p + 1][1] = bq[3];
            }
            #pragma unroll
            for (int f = 0; f < 4; ++f)
                #pragma unroll
                for (int j = 0; j < 8; ++j)
                    mma16(acc[f][j], af[f], bf[j]);
        }
    }

    // ---------------- epilogue ----------------
    const float* Bbias = bias + e * NTOT + n0;
    #pragma unroll
    for (int f = 0; f < 4; ++f) {
        const int rl = mb + f * 16 + g;
        #pragma unroll
        for (int j = 0; j < 8; ++j) {
            const int c = nb + j * 8 + 2 * tg;
            const float b0 = Bbias[c], b1 = Bbias[c + 1];
            float v00 = acc[f][j][0] + b0, v01 = acc[f][j][1] + b1;
            float v10 = acc[f][j][2] + b0, v11 = acc[f][j][3] + b1;
            if (RELU) {
                v00 = fmaxf(v00, 0.f); v01 = fmaxf(v01, 0.f);
                v10 = fmaxf(v10, 0.f); v11 = fmaxf(v11, 0.f);
            }
            if (STAGE == 3) {   // fp32 y output
                if (row0 + rl < cnt) {
                    float* p = g_y + ((size_t)e * CAP_ + row0 + rl) * NTOT + n0 + c;
                    p[0] = v00; p[1] = v01;
                }
                if (row0 + rl + 8 < cnt) {
                    float* p = g_y + ((size_t)e * CAP_ + row0 + rl + 8) * NTOT + n0 + c;
                    p[0] = v10; p[1] = v11;
                }
            } else {            // fp16 activations
                __half* Y = (STAGE == 1) ? g_h1h : g_h2h;
                if (row0 + rl < cnt)
                    *(__half2*)(Y + ((size_t)e * CAP_ + row0 + rl) * NTOT + n0 + c)
                        = __floats2half2_rn(v00, v01);
                if (row0 + rl + 8 < cnt)
                    *(__half2*)(Y + ((size_t)e * CAP_ + row0 + rl + 8) * NTOT + n0 + c)
                        = __floats2half2_rn(v10, v11);
            }
        }
    }
}

// ---------------- combine (+ finalize in block 0): out[t] = w1*y[p1] + w2*y[p2] ----------------
__global__ void __launch_bounds__(256) combine_kernel(float* __restrict__ out) {
    const int idx = blockIdx.x * blockDim.x + threadIdx.x;    // B_*64 threads
    const int t = idx >> 6, q = idx & 63;
    const int p0 = g_pos[t * 2], p1 = g_pos[t * 2 + 1];
    const float w0 = g_wtk[t * 2], w1 = g_wtk[t * 2 + 1];
    const float4 a = ((const float4*)g_y)[(size_t)p0 * 64 + q];
    const float4 b = ((const float4*)g_y)[(size_t)p1 * 64 + q];
    float4 o;
    o.x = w0 * a.x + w1 * b.x;
    o.y = w0 * a.y + w1 * b.y;
    o.z = w0 * a.z + w1 * b.z;
    o.w = w0 * a.w + w1 * b.w;
    ((float4*)out)[(size_t)t * 64 + q] = o;

    if (blockIdx.x == 0 && threadIdx.x == 0) {
        float us[E_];
        #pragma unroll
        for (int e2 = 0; e2 < E_; ++e2) {
            us[e2] = (float)g_counts[e2] / (float)B_;
            out[(size_t)B_ * D_OUT_ + 1 + e2] = us[e2];
        }
        float s = 0.f;
        #pragma unroll
        for (int i = 0; i < E_; ++i) { float d = us[i] - (1.f / E_); s += d * d; }
        out[(size_t)B_ * D_OUT_] = (s / E_) * 0.01f;
    }
}

// ---------------- launch (gemm1 at slot 4 for ncu capture) ----------------
extern "C" void kernel_launch(void* const* d_in, const int* in_sizes, int n_in,
                              void* d_out, int out_size) {
    const float* x   = (const float*)d_in[0];
    const float* gW1 = (const float*)d_in[1];
    const float* gb1 = (const float*)d_in[2];
    const float* gW2 = (const float*)d_in[3];
    const float* gb2 = (const float*)d_in[4];
    const float* We1 = (const float*)d_in[5];
    const float* be1 = (const float*)d_in[6];
    const float* We2 = (const float*)d_in[7];
    const float* be2 = (const float*)d_in[8];
    const float* We3 = (const float*)d_in[9];
    const float* be3 = (const float*)d_in[10];
    float* out = (float*)d_out;

    cudaFuncSetAttribute(gating_kernel, cudaFuncAttributeMaxDynamicSharedMemorySize,
                         GATE_DSMEM);
    cudaFuncSetAttribute(gemm_mma<256, 512, 1, true >,
                         cudaFuncAttributeMaxDynamicSharedMemorySize, GEMM_DSMEM);
    cudaFuncSetAttribute(gemm_mma<512, 512, 2, true >,
                         cudaFuncAttributeMaxDynamicSharedMemorySize, GEMM_DSMEM);
    cudaFuncSetAttribute(gemm_mma<512, 256, 3, false>,
                         cudaFuncAttributeMaxDynamicSharedMemorySize, GEMM_DSMEM);

    transpose_all<<<dim3(16, 16, 24), 256>>>(We1, We2, We3);            // 1 (+ zero counts)
    gating_kernel<<<256, 256, GATE_DSMEM>>>(x, gW1, gb1, gW2, gb2);     // 2
    gather_kernel<<<dim3(CAP_ / 64, E_), 256>>>(x);                     // 3
    gemm_mma<256, 512, 1, true ><<<dim3(4, CAP_ / 128, E_), 128, GEMM_DSMEM>>>(be1);  // 4 <- profiled
    gemm_mma<512, 512, 2, true ><<<dim3(4, CAP_ / 128, E_), 128, GEMM_DSMEM>>>(be2);  // 5
    gemm_mma<512, 256, 3, false><<<dim3(2, CAP_ / 128, E_), 128, GEMM_DSMEM>>>(be3);  // 6
    combine_kernel<<<B_ * 64 / 256, 256>>>(out);                        // 7 (+ finalize)
}